// round 4
// baseline (speedup 1.0000x reference)
#include <cuda_runtime.h>
#include <math.h>

#define Bq 512
#define Sq 4096
#define Dq 128
#define Vq 6
#define Kq 409

// ---------------------------------------------------------------------------
// Single fused kernel: one CTA per batch row, 256 threads.
//   phase 0: issue x-row loads (4 x LDG.128/thread), load emb to smem
//   phase 1-3: redundant per-CTA MLP precompute (scores + attended table),
//              overlapped with the in-flight x loads
//   phase 4: consume x: final_scores (SEL chain), histogram, scan,
//            stable-grouped top-k compaction, pooled+classifier epilogue
// ---------------------------------------------------------------------------
__global__ __launch_bounds__(256, 3) void fused_kernel(
    const int* __restrict__ x,
    const float* __restrict__ emb,
    const float* __restrict__ W1, const float* __restrict__ b1,
    const float* __restrict__ W2, const float* __restrict__ b2,
    const float* __restrict__ W3, const float* __restrict__ b3,
    const float* __restrict__ A1, const float* __restrict__ a1,
    const float* __restrict__ A2, const float* __restrict__ a2,
    const float* __restrict__ C1, const float* __restrict__ c1,
    const float* __restrict__ C2, const float* __restrict__ c2,
    float* __restrict__ out)
{
    const int b = blockIdx.x;
    const int t = threadIdx.x;  // 256 threads

    __shared__ float e_sm[Vq * Dq];     // 3 KB
    __shared__ float h1_sm[Vq * 64];
    __shared__ float g1_sm[Vq * 64];
    __shared__ float h2_sm[Vq * 32];
    __shared__ float att_sm[Vq * Dq];   // 3 KB
    __shared__ float score_sm[Vq];
    __shared__ int   cnt[Vq][256];      // 6 KB
    __shared__ int   take_sm[Vq], off_sm[Vq], tot_sm[Vq];
    __shared__ float sh_idx[Kq];
    __shared__ float pooled[Dq];
    __shared__ float hcls[64];

    // ---- phase 0: issue x loads early; they complete while MLP runs ----
    const int4* xb = (const int4*)(x + (size_t)b * Sq);
    int4 p0 = xb[t * 4 + 0];
    int4 p1 = xb[t * 4 + 1];
    int4 p2 = xb[t * 4 + 2];
    int4 p3 = xb[t * 4 + 3];

    // embedding table -> smem (768 floats, coalesced)
    e_sm[t]       = emb[t];
    e_sm[t + 256] = emb[t + 256];
    e_sm[t + 512] = emb[t + 512];
    __syncthreads();

    // ---- phase 1: layer1 (W1) + A1, 384 (v,n) tasks ----
    {
        #pragma unroll
        for (int rep = 0; rep < 2; rep++) {
            int task = t + rep * 256;
            if (task < Vq * 64) {
                const int v = task >> 6, n = task & 63;
                const float* ev = &e_sm[v * Dq];
                float s  = b1[n];
                float sa = a1[n];
                #pragma unroll 8
                for (int i = 0; i < Dq; i++) {
                    float ei = ev[i];
                    s  += ei * W1[i * 64 + n];
                    sa += ei * A1[i * 64 + n];
                }
                h1_sm[task] = fmaxf(s, 0.f);
                g1_sm[task] = fmaxf(sa, 0.f);
            }
        }
    }
    __syncthreads();

    // ---- phase 2: layer2 (W2, 192 tasks) and A2 (768 tasks) ----
    if (t < Vq * 32) {
        const int v = t >> 5, n = t & 31;
        float s = b2[n];
        #pragma unroll 8
        for (int i = 0; i < 64; i++) s += h1_sm[v * 64 + i] * W2[i * 32 + n];
        h2_sm[t] = fmaxf(s, 0.f);
    }
    {
        #pragma unroll
        for (int rep = 0; rep < 3; rep++) {
            int task = t + rep * 256;
            const int v = task >> 7, j = task & 127;
            float s = a2[j];
            #pragma unroll 8
            for (int i = 0; i < 64; i++) s += g1_sm[v * 64 + i] * A2[i * Dq + j];
            att_sm[task] = s;
        }
    }
    __syncthreads();

    // ---- phase 3: layer3 -> 6 sigmoid scores (warp per value) ----
    {
        const int wid = t >> 5, lane = t & 31;
        if (wid < Vq) {
            float z = h2_sm[wid * 32 + lane] * W3[lane];
            #pragma unroll
            for (int d = 16; d >= 1; d >>= 1) z += __shfl_xor_sync(0xffffffff, z, d);
            if (lane == 0) score_sm[wid] = 1.f / (1.f + expf(-(z + b3[0])));
        }
    }
    __syncthreads();

    // ---- phase 4: consume x ----
    const float s0 = score_sm[0], s1 = score_sm[1], s2 = score_sm[2];
    const float s3 = score_sm[3], s4 = score_sm[4], s5 = score_sm[5];

    int vals[16];
    vals[0]=p0.x; vals[1]=p0.y; vals[2]=p0.z; vals[3]=p0.w;
    vals[4]=p1.x; vals[5]=p1.y; vals[6]=p1.z; vals[7]=p1.w;
    vals[8]=p2.x; vals[9]=p2.y; vals[10]=p2.z; vals[11]=p2.w;
    vals[12]=p3.x; vals[13]=p3.y; vals[14]=p3.z; vals[15]=p3.w;

    float* fs = out + Bq + (size_t)Bq * Kq + (size_t)b * Sq;
    unsigned long long hist = 0ull;

    #pragma unroll
    for (int i = 0; i < 4; i++) {
        float4 f;
        float* fp = (float*)&f;
        #pragma unroll
        for (int j = 0; j < 4; j++) {
            const int v = vals[i * 4 + j];
            float sc = s0;
            sc = (v == 1) ? s1 : sc;
            sc = (v == 2) ? s2 : sc;
            sc = (v == 3) ? s3 : sc;
            sc = (v == 4) ? s4 : sc;
            sc = (v == 5) ? s5 : sc;
            fp[j] = sc;
            hist += 1ull << (v << 3);
        }
        ((float4*)fs)[t * 4 + i] = f;
    }
    #pragma unroll
    for (int v = 0; v < Vq; v++) cnt[v][t] = (int)((hist >> (v * 8)) & 0xFF);
    __syncthreads();

    // exclusive scan per token value: warp v scans cnt[v][0..255]
    const int wid = t >> 5, lane = t & 31;
    if (wid < Vq) {
        const int v = wid;
        int loc[8], s = 0;
        #pragma unroll
        for (int i = 0; i < 8; i++) { loc[i] = s; s += cnt[v][lane * 8 + i]; }
        int run = s;
        #pragma unroll
        for (int d = 1; d < 32; d <<= 1) {
            int o = __shfl_up_sync(0xffffffff, run, d);
            if (lane >= d) run += o;
        }
        const int excl = run - s;
        #pragma unroll
        for (int i = 0; i < 8; i++) cnt[v][lane * 8 + i] = excl + loc[i];
        if (lane == 31) tot_sm[v] = run;
    }
    __syncthreads();

    if (t == 0) {
        // stable descending order of the 6 scores (ties -> lower value index)
        int order[Vq];
        bool used[Vq];
        #pragma unroll
        for (int v = 0; v < Vq; v++) used[v] = false;
        #pragma unroll
        for (int g = 0; g < Vq; g++) {
            int best = 0; float bs = -1e30f;
            #pragma unroll
            for (int v = 0; v < Vq; v++)
                if (!used[v] && score_sm[v] > bs) { bs = score_sm[v]; best = v; }
            used[best] = true;
            order[g] = best;
        }
        int rem = Kq, off = 0;
        #pragma unroll
        for (int g = 0; g < Vq; g++) {
            int v = order[g];
            int tk = min(tot_sm[v], rem);
            take_sm[v] = tk; off_sm[v] = off;
            off += tk; rem -= tk;
        }
    }
    __syncthreads();

    // compaction into shared, then coalesced global write
    int ctr[Vq];
    #pragma unroll
    for (int v = 0; v < Vq; v++) ctr[v] = cnt[v][t];
    #pragma unroll
    for (int i = 0; i < 16; i++) {
        const int vv = vals[i];
        int rank = 0, tk = 0, off = 0;
        #pragma unroll
        for (int v = 0; v < Vq; v++)
            if (vv == v) { rank = ctr[v]++; tk = take_sm[v]; off = off_sm[v]; }
        if (rank < tk) sh_idx[off + rank] = (float)(t * 16 + i);
    }
    __syncthreads();

    float* oidx = out + Bq + (size_t)b * Kq;
    for (int j = t; j < Kq; j += 256) oidx[j] = sh_idx[j];

    // epilogue: pooled mean over selected attended rows
    if (t < Dq) {
        float s = 0.f;
        #pragma unroll
        for (int v = 0; v < Vq; v++)
            s += (float)take_sm[v] * att_sm[v * Dq + t];
        pooled[t] = s * (1.f / (float)Kq);
    }
    __syncthreads();

    // classifier layer 1: 64 neurons x 4 threads (32 inputs each)
    {
        const int n = t >> 2, q = t & 3;
        float s = 0.f;
        const int base = q * 32;
        #pragma unroll 8
        for (int i = 0; i < 32; i++)
            s += pooled[base + i] * C1[(base + i) * 64 + n];
        s += __shfl_xor_sync(0xffffffff, s, 1);
        s += __shfl_xor_sync(0xffffffff, s, 2);
        if (q == 0) hcls[n] = fmaxf(s + c1[n], 0.f);
    }
    __syncthreads();

    // classifier layer 2: one warp reduces 64 values
    if (t < 32) {
        float z = hcls[t] * C2[t] + hcls[t + 32] * C2[t + 32];
        #pragma unroll
        for (int d = 16; d >= 1; d >>= 1) z += __shfl_xor_sync(0xffffffff, z, d);
        if (t == 0) out[b] = 1.f / (1.f + expf(-(z + c2[0])));
    }
}

extern "C" void kernel_launch(void* const* d_in, const int* in_sizes, int n_in,
                              void* d_out, int out_size) {
    const int*   x   = (const int*)d_in[0];
    const float* emb = (const float*)d_in[1];
    const float* W1  = (const float*)d_in[2];
    const float* b1  = (const float*)d_in[3];
    const float* W2  = (const float*)d_in[4];
    const float* b2  = (const float*)d_in[5];
    const float* W3  = (const float*)d_in[6];
    const float* b3  = (const float*)d_in[7];
    const float* A1  = (const float*)d_in[8];
    const float* a1  = (const float*)d_in[9];
    const float* A2  = (const float*)d_in[10];
    const float* a2  = (const float*)d_in[11];
    const float* C1  = (const float*)d_in[12];
    const float* c1  = (const float*)d_in[13];
    const float* C2  = (const float*)d_in[14];
    const float* c2  = (const float*)d_in[15];
    float* out = (float*)d_out;

    fused_kernel<<<Bq, 256>>>(x, emb, W1, b1, W2, b2, W3, b3,
                              A1, a1, A2, a2, C1, c1, C2, c2, out);
}

// round 5
// speedup vs baseline: 1.8799x; 1.8799x over previous
#include <cuda_runtime.h>
#include <math.h>

#define Bq 512
#define Sq 4096
#define Dq 128
#define Vq 6
#define Kq 409

// Precomputed per-token-value tables
__device__ float g_score[Vq];
__device__ float g_att[Vq * Dq];

// ---------------------------------------------------------------------------
// Kernel 1: precompute — 6 blocks (one per token value) x 256 threads.
// Every dot product split across 2-4 threads, fully unrolled -> one memory
// round trip per layer instead of a 128-deep latency chain.
// ---------------------------------------------------------------------------
__global__ __launch_bounds__(256) void precompute_kernel(
    const float* __restrict__ emb,
    const float* __restrict__ W1, const float* __restrict__ b1,
    const float* __restrict__ W2, const float* __restrict__ b2,
    const float* __restrict__ W3, const float* __restrict__ b3,
    const float* __restrict__ A1, const float* __restrict__ a1,
    const float* __restrict__ A2, const float* __restrict__ a2)
{
    const int v = blockIdx.x;
    const int t = threadIdx.x;  // 256 threads
    __shared__ float e[Dq];
    __shared__ float h1[64];
    __shared__ float g1[64];
    __shared__ float h2[32];

    if (t < Dq) e[t] = emb[v * Dq + t];
    __syncthreads();

    // layer 1: both W1 and A1. 256 threads = 2 mats x 64 neurons x 2 halves.
    {
        const int mat = t >> 7;          // 0 -> W1 path, 1 -> A1 path
        const int n   = (t & 127) >> 1;  // neuron 0..63
        const int p   = t & 1;           // half 0..1
        const float* M = mat ? A1 : W1;
        float s = 0.f;
        const int base = p * 64;
        #pragma unroll
        for (int i = 0; i < 64; i++)
            s += e[base + i] * M[(base + i) * 64 + n];
        s += __shfl_xor_sync(0xffffffff, s, 1);
        if (p == 0) {
            if (mat == 0) h1[n] = fmaxf(s + b1[n], 0.f);
            else          g1[n] = fmaxf(s + a1[n], 0.f);
        }
    }
    __syncthreads();

    // layer 2 (W2): 32 neurons x 4 threads (uses threads 0..127)
    if (t < 128) {
        const int n = t >> 2, p = t & 3;
        float s = 0.f;
        const int base = p * 16;
        #pragma unroll
        for (int i = 0; i < 16; i++)
            s += h1[base + i] * W2[(base + i) * 32 + n];
        s += __shfl_xor_sync(0xffffffff, s, 1);
        s += __shfl_xor_sync(0xffffffff, s, 2);
        if (p == 0) h2[n] = fmaxf(s + b2[n], 0.f);
    }
    // A2: 128 outputs x 2 threads (all 256 threads)
    {
        const int j = t >> 1, p = t & 1;
        float s = 0.f;
        const int base = p * 32;
        #pragma unroll
        for (int i = 0; i < 32; i++)
            s += g1[base + i] * A2[(base + i) * Dq + j];
        s += __shfl_xor_sync(0xffffffff, s, 1);
        if (p == 0) g_att[v * Dq + j] = s + a2[j];
    }
    __syncthreads();

    // layer 3: warp 0 reduces 32 values -> sigmoid score
    if (t < 32) {
        float z = h2[t] * W3[t];
        #pragma unroll
        for (int d = 16; d >= 1; d >>= 1) z += __shfl_xor_sync(0xffffffff, z, d);
        if (t == 0) g_score[v] = 1.f / (1.f + expf(-(z + b3[0])));
    }
}

// ---------------------------------------------------------------------------
// Kernel 2: one CTA per batch row. 512 threads, 8 tokens/thread.
// ---------------------------------------------------------------------------
__global__ __launch_bounds__(512) void main_kernel(
    const int* __restrict__ x,
    const float* __restrict__ C1, const float* __restrict__ c1,
    const float* __restrict__ C2, const float* __restrict__ c2,
    float* __restrict__ out)
{
    const int b = blockIdx.x;
    const int t = threadIdx.x;  // 512 threads

    __shared__ int   cnt[Vq][512];      // 12 KB
    __shared__ float score_sm[Vq];
    __shared__ int   take_sm[Vq], off_sm[Vq], tot_sm[Vq];
    __shared__ float sh_idx[Kq];
    __shared__ float pooled[Dq];
    __shared__ float hcls[64];

    if (t < Vq) score_sm[t] = g_score[t];
    __syncthreads();

    const int4* xb = (const int4*)(x + (size_t)b * Sq);
    float* fs = out + Bq + (size_t)Bq * Kq + (size_t)b * Sq;

    int vals[8];
    unsigned long long hist = 0ull;

    #pragma unroll
    for (int i = 0; i < 2; i++) {
        int4 p = xb[t * 2 + i];
        vals[i * 4 + 0] = p.x; vals[i * 4 + 1] = p.y;
        vals[i * 4 + 2] = p.z; vals[i * 4 + 3] = p.w;
        float4 f;
        f.x = score_sm[p.x]; f.y = score_sm[p.y];
        f.z = score_sm[p.z]; f.w = score_sm[p.w];
        ((float4*)fs)[t * 2 + i] = f;
        hist += 1ull << (p.x << 3);
        hist += 1ull << (p.y << 3);
        hist += 1ull << (p.z << 3);
        hist += 1ull << (p.w << 3);
    }
    #pragma unroll
    for (int v = 0; v < Vq; v++) cnt[v][t] = (int)((hist >> (v * 8)) & 0xFF);
    __syncthreads();

    // exclusive scan per token value: warp v scans cnt[v][0..511]
    const int wid = t >> 5, lane = t & 31;
    if (wid < Vq) {
        const int v = wid;
        int loc[16], s = 0;
        #pragma unroll
        for (int i = 0; i < 16; i++) { loc[i] = s; s += cnt[v][lane * 16 + i]; }
        int run = s;
        #pragma unroll
        for (int d = 1; d < 32; d <<= 1) {
            int o = __shfl_up_sync(0xffffffff, run, d);
            if (lane >= d) run += o;
        }
        const int excl = run - s;
        #pragma unroll
        for (int i = 0; i < 16; i++) cnt[v][lane * 16 + i] = excl + loc[i];
        if (lane == 31) tot_sm[v] = run;
    }
    __syncthreads();

    if (t == 0) {
        // stable descending order of the 6 scores (ties -> lower value index)
        int order[Vq];
        bool used[Vq];
        #pragma unroll
        for (int v = 0; v < Vq; v++) used[v] = false;
        #pragma unroll
        for (int g = 0; g < Vq; g++) {
            int best = 0; float bs = -1e30f;
            #pragma unroll
            for (int v = 0; v < Vq; v++)
                if (!used[v] && score_sm[v] > bs) { bs = score_sm[v]; best = v; }
            used[best] = true;
            order[g] = best;
        }
        int rem = Kq, off = 0;
        #pragma unroll
        for (int g = 0; g < Vq; g++) {
            int v = order[g];
            int tk = min(tot_sm[v], rem);
            take_sm[v] = tk; off_sm[v] = off;
            off += tk; rem -= tk;
        }
    }
    __syncthreads();

    // compaction into shared, then coalesced global write
    int ctr[Vq];
    #pragma unroll
    for (int v = 0; v < Vq; v++) ctr[v] = cnt[v][t];
    #pragma unroll
    for (int i = 0; i < 8; i++) {
        const int vv = vals[i];
        int rank = 0, tk = 0, off = 0;
        #pragma unroll
        for (int v = 0; v < Vq; v++)
            if (vv == v) { rank = ctr[v]++; tk = take_sm[v]; off = off_sm[v]; }
        if (rank < tk) sh_idx[off + rank] = (float)(t * 8 + i);
    }
    __syncthreads();

    float* oidx = out + Bq + (size_t)b * Kq;
    if (t < Kq) oidx[t] = sh_idx[t];

    // epilogue: pooled mean over selected attended rows
    if (t < Dq) {
        float s = 0.f;
        #pragma unroll
        for (int v = 0; v < Vq; v++)
            s += (float)take_sm[v] * g_att[v * Dq + t];
        pooled[t] = s * (1.f / (float)Kq);
    }
    __syncthreads();

    // classifier layer 1: 64 neurons x 8 threads (16 inputs each)
    {
        const int n = t >> 3, q = t & 7;
        float s = 0.f;
        const int base = q * 16;
        #pragma unroll
        for (int i = 0; i < 16; i++)
            s += pooled[base + i] * C1[(base + i) * 64 + n];
        s += __shfl_xor_sync(0xffffffff, s, 1);
        s += __shfl_xor_sync(0xffffffff, s, 2);
        s += __shfl_xor_sync(0xffffffff, s, 4);
        if (q == 0) hcls[n] = fmaxf(s + c1[n], 0.f);
    }
    __syncthreads();

    // classifier layer 2: one warp reduces 64 values
    if (t < 32) {
        float z = hcls[t] * C2[t] + hcls[t + 32] * C2[t + 32];
        #pragma unroll
        for (int d = 16; d >= 1; d >>= 1) z += __shfl_xor_sync(0xffffffff, z, d);
        if (t == 0) out[b] = 1.f / (1.f + expf(-(z + c2[0])));
    }
}

extern "C" void kernel_launch(void* const* d_in, const int* in_sizes, int n_in,
                              void* d_out, int out_size) {
    const int*   x   = (const int*)d_in[0];
    const float* emb = (const float*)d_in[1];
    const float* W1  = (const float*)d_in[2];
    const float* b1  = (const float*)d_in[3];
    const float* W2  = (const float*)d_in[4];
    const float* b2  = (const float*)d_in[5];
    const float* W3  = (const float*)d_in[6];
    const float* b3  = (const float*)d_in[7];
    const float* A1  = (const float*)d_in[8];
    const float* a1  = (const float*)d_in[9];
    const float* A2  = (const float*)d_in[10];
    const float* a2  = (const float*)d_in[11];
    const float* C1  = (const float*)d_in[12];
    const float* c1  = (const float*)d_in[13];
    const float* C2  = (const float*)d_in[14];
    const float* c2  = (const float*)d_in[15];
    float* out = (float*)d_out;

    precompute_kernel<<<Vq, 256>>>(emb, W1, b1, W2, b2, W3, b3, A1, a1, A2, a2);
    main_kernel<<<Bq, 512>>>(x, C1, c1, C2, c2, out);
}